// round 14
// baseline (speedup 1.0000x reference)
#include <cuda_runtime.h>
#include <cuda_bf16.h>
#include <cstdint>

// FastVCompressor v7: bf16 HMMA screening + exact fp32 rescore.
// vs v5 (155.7us): triple-buffered cp.async pipeline, prefetch distance 2
// (wait_group 1) — doubles the DRAM-latency hiding window per chunk.
// (v6 fp8 regressed to 168us: convert-ALU cost + coarser chunks; reverted.)
//   keys   [4,4096,1024] f32 = d_in[0]
//   values [4,4096,1024] f32 = d_in[1]
//   codebook [256,1024]  f32 = d_in[2]
//   out = keys_c ++ values_c (32M floats)

#define H      1024
#define CODES  256
#define MROWS  64          // rows per CTA
#define NKC    64          // k16 chunks
#define BUFB   12288       // one chunk of bf16-hi codebook: 256 codes * 48B
#define XBUFB  5120        // one X chunk: 64 rows * 20 floats (16 data + 4 pad)
#define NCAND  24
#define MARGIN 2.0f        // ~25 sigma of bf16 screening error

// ---- smem layout ----
#define SO_IDX    0                      // 64 ints: final winner per row
#define SO_CNT    256                    // 64 ints: candidate counts
#define SO_RMIN   512                    // 64 floats: screened min per row
#define SO_CSQ    768                    // 256 floats
#define SO_WVAL   1792                   // 64*8 floats: per-warp row mins
#define SO_CAND   3840                   // 64*24 ints = 6144
#define SO_CBUF   9984                   // 3*BUFB = 36864 (128B aligned)
#define SO_XS     46848                  // 3*XBUFB = 15360 (128B aligned)
#define XS_STRIDE 20
#define SMEM_TOTAL 62208

__device__ float g_csq[CODES];
__device__ __align__(128) unsigned char g_bsplit[NKC * BUFB];   // 768 KB (L2-resident)

// ---------------------------------------------------------------- helpers
static __device__ __forceinline__ uint32_t smem_u32(const void* p) {
    uint32_t a;
    asm("{ .reg .u64 t; cvta.to.shared.u64 t, %1; cvt.u32.u64 %0, t; }"
        : "=r"(a) : "l"(p));
    return a;
}

#define CPA16(dst, src) \
    asm volatile("cp.async.cg.shared.global [%0], [%1], 16;" \
                 :: "r"(dst), "l"(src) : "memory")
#define CPA_COMMIT() asm volatile("cp.async.commit_group;" ::: "memory")
#define CPA_WAIT(n)  asm volatile("cp.async.wait_group %0;" :: "n"(n) : "memory")

#define LDSM4(r0, r1, r2, r3, addr)                                             \
    asm volatile("ldmatrix.sync.aligned.m8n8.x4.shared.b16 {%0,%1,%2,%3}, [%4];" \
        : "=r"(r0), "=r"(r1), "=r"(r2), "=r"(r3) : "r"(addr))

#define MMA4(c, a0, a1, a2, a3, b0, b1)                                         \
    asm volatile("mma.sync.aligned.m16n8k16.row.col.f32.bf16.bf16.f32 "         \
        "{%0,%1,%2,%3}, {%4,%5,%6,%7}, {%8,%9}, {%0,%1,%2,%3};"                 \
        : "+f"((c)[0]), "+f"((c)[1]), "+f"((c)[2]), "+f"((c)[3])                \
        : "r"(a0), "r"(a1), "r"(a2), "r"(a3), "r"(b0), "r"(b1))

#define CVT2(d, hi, lo) \
    asm("cvt.rn.bf16x2.f32 %0, %1, %2;" : "=r"(d) : "f"(hi), "f"(lo))

// ---------------------------------------------------------------- prep: c_sq
__global__ void csq_kernel(const float* __restrict__ cb) {
    const int c = blockIdx.x;
    const float4 v = ((const float4*)(cb + (size_t)c * H))[threadIdx.x];
    float s = v.x * v.x + v.y * v.y + v.z * v.z + v.w * v.w;
    #pragma unroll
    for (int o = 16; o; o >>= 1) s += __shfl_xor_sync(0xffffffffu, s, o);
    __shared__ float ws[8];
    if ((threadIdx.x & 31) == 0) ws[threadIdx.x >> 5] = s;
    __syncthreads();
    if (threadIdx.x == 0) {
        float t = 0.f;
        #pragma unroll
        for (int i = 0; i < 8; ++i) t += ws[i];
        g_csq[c] = t;
    }
}

// ------------------------------------------- prep: codebook bf16-hi, 48B rows
__global__ void bprep_kernel(const float* __restrict__ cb) {
    const int code = blockIdx.x;
    const float4 v = ((const float4*)(cb + (size_t)code * H))[threadIdx.x];
    const float f[4] = {v.x, v.y, v.z, v.w};
    #pragma unroll
    for (int e = 0; e < 4; ++e) {
        const int k = threadIdx.x * 4 + e;
        *(__nv_bfloat16*)(g_bsplit + (size_t)(k >> 4) * BUFB + code * 48 + (k & 15) * 2)
            = __float2bfloat16(f[e]);
    }
}

// ---------------------------------------------------------------- main VQ
__global__ __launch_bounds__(256, 2) void vq_kernel(
    const float* __restrict__ keys, const float* __restrict__ values,
    const float* __restrict__ cb, float* __restrict__ out)
{
    extern __shared__ char smem[];
    const uint32_t sb = smem_u32(smem);
    const int tid = threadIdx.x, lane = tid & 31, nw = tid >> 5;
    const int bid = blockIdx.x;

    const float* src = (bid < 256) ? keys   + (size_t)bid * MROWS * H
                                   : values + (size_t)(bid - 256) * MROWS * H;

    const int xrow = tid >> 2, xc4 = (tid & 3) * 4;
    const uint32_t xs_off = (uint32_t)(xrow * XS_STRIDE + xc4) * 4u;

    // prologue: issue chunks 0 and 1 as two separate groups (3 buffers)
    #pragma unroll
    for (int pc = 0; pc < 2; ++pc) {
        const unsigned char* sg = g_bsplit + (size_t)pc * BUFB;
        const uint32_t dstb = sb + SO_CBUF + (uint32_t)pc * BUFB;
        #pragma unroll
        for (int j = 0; j < 3; ++j) {
            const uint32_t o = (uint32_t)(tid + 256 * j) * 16u;
            CPA16(dstb + o, sg + o);
        }
        CPA16(sb + SO_XS + (uint32_t)pc * XBUFB + xs_off,
              src + (size_t)xrow * H + pc * 16 + xc4);
        CPA_COMMIT();
    }

    float acc[4][4][4];
    #pragma unroll
    for (int a = 0; a < 4; ++a)
        #pragma unroll
        for (int b = 0; b < 4; ++b)
            #pragma unroll
            for (int c = 0; c < 4; ++c) acc[a][b][c] = 0.f;

    const uint32_t laneoff = (uint32_t)nw * 1536u
        + (uint32_t)((lane & 7) + ((lane >> 4) << 3)) * 48u
        + (uint32_t)((lane >> 3) & 1) * 16u;
    const int r0 = lane >> 2, c0 = (lane & 3) * 2;

    int bcur = 0, bpre = 2;   // buffer of chunk kc; buffer for chunk kc+2
    for (int kc = 0; kc < NKC; ++kc) {
        if (kc + 1 < NKC) CPA_WAIT(1);   // chunk kc resident; kc+1 may fly
        else              CPA_WAIT(0);
        __syncthreads();                 // visibility + WAR on buf bpre

        if (kc + 2 < NKC) {  // prefetch chunk kc+2 -> buf bpre
            const unsigned char* sg = g_bsplit + (size_t)(kc + 2) * BUFB;
            const uint32_t dstb = sb + SO_CBUF + (uint32_t)bpre * BUFB;
            #pragma unroll
            for (int j = 0; j < 3; ++j) {
                const uint32_t o = (uint32_t)(tid + 256 * j) * 16u;
                CPA16(dstb + o, sg + o);
            }
            CPA16(sb + SO_XS + (uint32_t)bpre * XBUFB + xs_off,
                  src + (size_t)xrow * H + (kc + 2) * 16 + xc4);
            CPA_COMMIT();
        }

        // B fragments
        const uint32_t bb = sb + SO_CBUF + (uint32_t)bcur * BUFB;
        uint32_t b0, b1, b2, b3, b4, b5, b6, b7;
        LDSM4(b0, b1, b2, b3, bb + 0 * 768 + laneoff);
        LDSM4(b4, b5, b6, b7, bb + 1 * 768 + laneoff);

        // bf16-hi of X chunk kc -> A fragments
        uint32_t ah[16];
        const float* xbuf = (const float*)(smem + SO_XS + bcur * XBUFB);
        #pragma unroll
        for (int mt = 0; mt < 4; ++mt)
            #pragma unroll
            for (int i = 0; i < 4; ++i) {
                const int rr = mt * 16 + r0 + (i & 1) * 8;
                const float2 v = *(const float2*)&xbuf[rr * XS_STRIDE + c0 + (i >> 1) * 8];
                CVT2(ah[mt * 4 + i], v.y, v.x);
            }

        #pragma unroll
        for (int mt = 0; mt < 4; ++mt) {
            MMA4(acc[mt][0], ah[mt*4+0], ah[mt*4+1], ah[mt*4+2], ah[mt*4+3], b0, b1);
            MMA4(acc[mt][1], ah[mt*4+0], ah[mt*4+1], ah[mt*4+2], ah[mt*4+3], b2, b3);
            MMA4(acc[mt][2], ah[mt*4+0], ah[mt*4+1], ah[mt*4+2], ah[mt*4+3], b4, b5);
            MMA4(acc[mt][3], ah[mt*4+0], ah[mt*4+1], ah[mt*4+2], ah[mt*4+3], b6, b7);
        }

        bcur = (bcur == 2) ? 0 : bcur + 1;
        bpre = (bpre == 2) ? 0 : bpre + 1;
    }

    // ---------------- epilogue: screen -> candidates -> exact rescore ------
    float* csq_s  = (float*)(smem + SO_CSQ);
    float* wval   = (float*)(smem + SO_WVAL);
    float* rmin   = (float*)(smem + SO_RMIN);
    int*   cnt    = (int*)(smem + SO_CNT);
    int*   cand   = (int*)(smem + SO_CAND);
    int*   idxs   = (int*)(smem + SO_IDX);

    __syncthreads();
    csq_s[tid] = g_csq[tid];
    if (tid < MROWS) cnt[tid] = 0;
    __syncthreads();

    // pass 1: per-warp min of screened distance per row
    #pragma unroll
    for (int mt = 0; mt < 4; ++mt)
        #pragma unroll
        for (int h = 0; h < 2; ++h) {
            const int row = mt * 16 + r0 + h * 8;
            float bv = 3.4e38f;
            #pragma unroll
            for (int nt = 0; nt < 4; ++nt) {
                const int col = nw * 32 + nt * 8 + c0;
                const float d0 = csq_s[col]     - 2.0f * acc[mt][nt][2*h];
                const float d1 = csq_s[col + 1] - 2.0f * acc[mt][nt][2*h+1];
                bv = fminf(bv, fminf(d0, d1));
            }
            bv = fminf(bv, __shfl_xor_sync(0xffffffffu, bv, 1));
            bv = fminf(bv, __shfl_xor_sync(0xffffffffu, bv, 2));
            if ((lane & 3) == 0) wval[row * 8 + nw] = bv;
        }
    __syncthreads();
    if (tid < MROWS) {
        float m = wval[tid * 8];
        #pragma unroll
        for (int w = 1; w < 8; ++w) m = fminf(m, wval[tid * 8 + w]);
        rmin[tid] = m;
    }
    __syncthreads();

    // pass 2: append candidates within MARGIN of the screened min
    #pragma unroll
    for (int mt = 0; mt < 4; ++mt)
        #pragma unroll
        for (int h = 0; h < 2; ++h) {
            const int row = mt * 16 + r0 + h * 8;
            const float thr = rmin[row] + MARGIN;
            #pragma unroll
            for (int nt = 0; nt < 4; ++nt) {
                const int col = nw * 32 + nt * 8 + c0;
                const float d0 = csq_s[col]     - 2.0f * acc[mt][nt][2*h];
                const float d1 = csq_s[col + 1] - 2.0f * acc[mt][nt][2*h+1];
                if (d0 <= thr) {
                    const int p = atomicAdd(&cnt[row], 1);
                    if (p < NCAND) cand[row * NCAND + p] = col;
                }
                if (d1 <= thr) {
                    const int p = atomicAdd(&cnt[row], 1);
                    if (p < NCAND) cand[row * NCAND + p] = col + 1;
                }
            }
        }
    __syncthreads();

    // rescore: warp nw owns rows nw*8..nw*8+7; exact fp32 distance.
    // Overflow (cnt > NCAND) falls back to exact scan of all 256 codes.
    const float4* cb4 = (const float4*)cb;
    for (int rr = 0; rr < 8; ++rr) {
        const int row = nw * 8 + rr;
        const int n = cnt[row];
        int winner;
        if (n <= 1) {
            winner = (n == 1) ? cand[row * NCAND] : 0;
        } else {
            const bool full = (n > NCAND);
            const int m = full ? CODES : n;
            float4 xr[8];
            const float4* xp = (const float4*)(src + (size_t)row * H);
            #pragma unroll
            for (int t = 0; t < 8; ++t) xr[t] = __ldg(xp + lane + 32 * t);
            float best = 3.4e38f; int bi = CODES;
            for (int j = 0; j < m; ++j) {
                const int c = full ? j : cand[row * NCAND + j];
                float p = 0.f;
                #pragma unroll
                for (int t = 0; t < 8; ++t) {
                    const float4 cv = __ldg(cb4 + (size_t)c * (H / 4) + lane + 32 * t);
                    p += xr[t].x * cv.x + xr[t].y * cv.y
                       + xr[t].z * cv.z + xr[t].w * cv.w;
                }
                #pragma unroll
                for (int o = 16; o; o >>= 1) p += __shfl_xor_sync(0xffffffffu, p, o);
                const float d = csq_s[c] - 2.0f * p;
                if (d < best || (d == best && c < bi)) { best = d; bi = c; }
            }
            winner = bi;
        }
        if (lane == 0) idxs[row] = winner;
    }
    __syncthreads();

    // gather winning codebook rows, apply sparsity mask, write coalesced
    float4* o4 = (float4*)out + (size_t)bid * MROWS * (H / 4);
    for (int r = 0; r < MROWS; ++r) {
        const int idx = idxs[r];
        const float sc = (csq_s[idx] > 0.01f) ? 1.0f : 0.0f;   // ||c|| > 0.1
        float4 v = cb4[(size_t)idx * (H / 4) + tid];
        v.x *= sc; v.y *= sc; v.z *= sc; v.w *= sc;
        o4[(size_t)r * (H / 4) + tid] = v;
    }
}

// ---------------------------------------------------------------- launch
extern "C" void kernel_launch(void* const* d_in, const int* in_sizes, int n_in,
                              void* d_out, int out_size) {
    const float* keys     = (const float*)d_in[0];
    const float* values   = (const float*)d_in[1];
    const float* codebook = (const float*)d_in[2];
    float* out = (float*)d_out;
    (void)in_sizes; (void)n_in; (void)out_size;

    cudaFuncSetAttribute(vq_kernel, cudaFuncAttributeMaxDynamicSharedMemorySize, SMEM_TOTAL);
    csq_kernel<<<CODES, 256>>>(codebook);
    bprep_kernel<<<CODES, 256>>>(codebook);
    vq_kernel<<<512, 256, SMEM_TOTAL>>>(keys, values, codebook, out);
}

// round 16
// speedup vs baseline: 1.5000x; 1.5000x over previous
#include <cuda_runtime.h>
#include <cuda_bf16.h>
#include <cstdint>

// FastVCompressor v8: v5 mainloop (bf16 HMMA screen, double-buffer cp.async,
// 155.7us proven) + rebuilt epilogue:
//   - rescore and gather fused per warp (all lanes agree on winner via
//     bit-identical butterfly reduce; no idx smem round-trip, no final barrier)
//   - gather: warp-per-row, 8 independent LDG.128+STG.128 (MLP 8) instead of
//     a 64-iteration serial block-wide dependent loop
// (v7 triple-buffer regressed -> mainloop is tensor-bound, not copy-bound.)
//   keys   [4,4096,1024] f32 = d_in[0]
//   values [4,4096,1024] f32 = d_in[1]
//   codebook [256,1024]  f32 = d_in[2]
//   out = keys_c ++ values_c (32M floats)

#define H      1024
#define CODES  256
#define MROWS  64          // rows per CTA
#define NKC    64          // k16 chunks
#define BUFB   12288       // one chunk of bf16-hi codebook: 256 codes * 48B
#define NCAND  24
#define MARGIN 2.0f        // ~25 sigma of bf16 screening error

// ---- smem layout ----
#define SO_CNT    256                    // 64 ints: candidate counts
#define SO_RMIN   512                    // 64 floats: screened min per row
#define SO_CSQ    768                    // 256 floats
#define SO_WVAL   1792                   // 64*8 floats: per-warp row mins
#define SO_CAND   3840                   // 64*24 ints = 6144
#define SO_CBUF   9984                   // 2*BUFB = 24576 (128B aligned)
#define SO_XS     34560                  // Xs[2][64][20] f32 = 10240
#define XS_HALF   1280
#define XS_STRIDE 20
#define SMEM_TOTAL 44800

__device__ float g_csq[CODES];
__device__ __align__(128) unsigned char g_bsplit[NKC * BUFB];   // 768 KB (L2-resident)

// ---------------------------------------------------------------- helpers
static __device__ __forceinline__ uint32_t smem_u32(const void* p) {
    uint32_t a;
    asm("{ .reg .u64 t; cvta.to.shared.u64 t, %1; cvt.u32.u64 %0, t; }"
        : "=r"(a) : "l"(p));
    return a;
}

#define CPA16(dst, src) \
    asm volatile("cp.async.cg.shared.global [%0], [%1], 16;" \
                 :: "r"(dst), "l"(src) : "memory")
#define CPA_COMMIT() asm volatile("cp.async.commit_group;" ::: "memory")
#define CPA_WAIT0()  asm volatile("cp.async.wait_group 0;" ::: "memory")

#define LDSM4(r0, r1, r2, r3, addr)                                             \
    asm volatile("ldmatrix.sync.aligned.m8n8.x4.shared.b16 {%0,%1,%2,%3}, [%4];" \
        : "=r"(r0), "=r"(r1), "=r"(r2), "=r"(r3) : "r"(addr))

#define MMA4(c, a0, a1, a2, a3, b0, b1)                                         \
    asm volatile("mma.sync.aligned.m16n8k16.row.col.f32.bf16.bf16.f32 "         \
        "{%0,%1,%2,%3}, {%4,%5,%6,%7}, {%8,%9}, {%0,%1,%2,%3};"                 \
        : "+f"((c)[0]), "+f"((c)[1]), "+f"((c)[2]), "+f"((c)[3])                \
        : "r"(a0), "r"(a1), "r"(a2), "r"(a3), "r"(b0), "r"(b1))

#define CVT2(d, hi, lo) \
    asm("cvt.rn.bf16x2.f32 %0, %1, %2;" : "=r"(d) : "f"(hi), "f"(lo))

// ---------------------------------------------------------------- prep: c_sq
__global__ void csq_kernel(const float* __restrict__ cb) {
    const int c = blockIdx.x;
    const float4 v = ((const float4*)(cb + (size_t)c * H))[threadIdx.x];
    float s = v.x * v.x + v.y * v.y + v.z * v.z + v.w * v.w;
    #pragma unroll
    for (int o = 16; o; o >>= 1) s += __shfl_xor_sync(0xffffffffu, s, o);
    __shared__ float ws[8];
    if ((threadIdx.x & 31) == 0) ws[threadIdx.x >> 5] = s;
    __syncthreads();
    if (threadIdx.x == 0) {
        float t = 0.f;
        #pragma unroll
        for (int i = 0; i < 8; ++i) t += ws[i];
        g_csq[c] = t;
    }
}

// ------------------------------------------- prep: codebook bf16-hi, 48B rows
__global__ void bprep_kernel(const float* __restrict__ cb) {
    const int code = blockIdx.x;
    const float4 v = ((const float4*)(cb + (size_t)code * H))[threadIdx.x];
    const float f[4] = {v.x, v.y, v.z, v.w};
    #pragma unroll
    for (int e = 0; e < 4; ++e) {
        const int k = threadIdx.x * 4 + e;
        *(__nv_bfloat16*)(g_bsplit + (size_t)(k >> 4) * BUFB + code * 48 + (k & 15) * 2)
            = __float2bfloat16(f[e]);
    }
}

// ---------------------------------------------------------------- main VQ
__global__ __launch_bounds__(256, 2) void vq_kernel(
    const float* __restrict__ keys, const float* __restrict__ values,
    const float* __restrict__ cb, float* __restrict__ out)
{
    extern __shared__ char smem[];
    const uint32_t sb = smem_u32(smem);
    const int tid = threadIdx.x, lane = tid & 31, nw = tid >> 5;
    const int bid = blockIdx.x;

    const float* src = (bid < 256) ? keys   + (size_t)bid * MROWS * H
                                   : values + (size_t)(bid - 256) * MROWS * H;

    const int xrow = tid >> 2, xc4 = (tid & 3) * 4;
    const uint32_t xs_off = (uint32_t)(xrow * XS_STRIDE + xc4) * 4u;

    // prologue: chunk 0 (B: 3x16B, X: 1x16B per thread) via cp.async
    #pragma unroll
    for (int j = 0; j < 3; ++j) {
        const uint32_t o = (uint32_t)(tid + 256 * j) * 16u;
        CPA16(sb + SO_CBUF + o, g_bsplit + o);
    }
    CPA16(sb + SO_XS + xs_off, src + (size_t)xrow * H + xc4);
    CPA_COMMIT();

    float acc[4][4][4];
    #pragma unroll
    for (int a = 0; a < 4; ++a)
        #pragma unroll
        for (int b = 0; b < 4; ++b)
            #pragma unroll
            for (int c = 0; c < 4; ++c) acc[a][b][c] = 0.f;

    const uint32_t laneoff = (uint32_t)nw * 1536u
        + (uint32_t)((lane & 7) + ((lane >> 4) << 3)) * 48u
        + (uint32_t)((lane >> 3) & 1) * 16u;
    const int r0 = lane >> 2, c0 = (lane & 3) * 2;

    for (int kc = 0; kc < NKC; ++kc) {
        const int b = kc & 1;
        CPA_WAIT0();
        __syncthreads();

        if (kc + 1 < NKC) {  // prefetch chunk kc+1 -> buf b^1
            const unsigned char* sg = g_bsplit + (size_t)(kc + 1) * BUFB;
            const uint32_t dstb = sb + SO_CBUF + (uint32_t)(b ^ 1) * BUFB;
            #pragma unroll
            for (int j = 0; j < 3; ++j) {
                const uint32_t o = (uint32_t)(tid + 256 * j) * 16u;
                CPA16(dstb + o, sg + o);
            }
            CPA16(sb + SO_XS + (uint32_t)(b ^ 1) * (XS_HALF * 4) + xs_off,
                  src + (size_t)xrow * H + (kc + 1) * 16 + xc4);
            CPA_COMMIT();
        }

        // B fragments
        const uint32_t bb = sb + SO_CBUF + (uint32_t)b * BUFB;
        uint32_t b0, b1, b2, b3, b4, b5, b6, b7;
        LDSM4(b0, b1, b2, b3, bb + 0 * 768 + laneoff);
        LDSM4(b4, b5, b6, b7, bb + 1 * 768 + laneoff);

        // bf16-hi of X chunk kc -> A fragments
        uint32_t ah[16];
        const float* xbuf = (const float*)(smem + SO_XS) + b * XS_HALF;
        #pragma unroll
        for (int mt = 0; mt < 4; ++mt)
            #pragma unroll
            for (int i = 0; i < 4; ++i) {
                const int rr = mt * 16 + r0 + (i & 1) * 8;
                const float2 v = *(const float2*)&xbuf[rr * XS_STRIDE + c0 + (i >> 1) * 8];
                CVT2(ah[mt * 4 + i], v.y, v.x);
            }

        #pragma unroll
        for (int mt = 0; mt < 4; ++mt) {
            MMA4(acc[mt][0], ah[mt*4+0], ah[mt*4+1], ah[mt*4+2], ah[mt*4+3], b0, b1);
            MMA4(acc[mt][1], ah[mt*4+0], ah[mt*4+1], ah[mt*4+2], ah[mt*4+3], b2, b3);
            MMA4(acc[mt][2], ah[mt*4+0], ah[mt*4+1], ah[mt*4+2], ah[mt*4+3], b4, b5);
            MMA4(acc[mt][3], ah[mt*4+0], ah[mt*4+1], ah[mt*4+2], ah[mt*4+3], b6, b7);
        }
    }

    // ---------------- epilogue: screen -> candidates -> rescore+gather ------
    float* csq_s  = (float*)(smem + SO_CSQ);
    float* wval   = (float*)(smem + SO_WVAL);
    float* rmin   = (float*)(smem + SO_RMIN);
    int*   cnt    = (int*)(smem + SO_CNT);
    int*   cand   = (int*)(smem + SO_CAND);

    __syncthreads();
    csq_s[tid] = g_csq[tid];
    if (tid < MROWS) cnt[tid] = 0;
    __syncthreads();

    // pass 1: per-warp min of screened distance per row
    #pragma unroll
    for (int mt = 0; mt < 4; ++mt)
        #pragma unroll
        for (int h = 0; h < 2; ++h) {
            const int row = mt * 16 + r0 + h * 8;
            float bv = 3.4e38f;
            #pragma unroll
            for (int nt = 0; nt < 4; ++nt) {
                const int col = nw * 32 + nt * 8 + c0;
                const float d0 = csq_s[col]     - 2.0f * acc[mt][nt][2*h];
                const float d1 = csq_s[col + 1] - 2.0f * acc[mt][nt][2*h+1];
                bv = fminf(bv, fminf(d0, d1));
            }
            bv = fminf(bv, __shfl_xor_sync(0xffffffffu, bv, 1));
            bv = fminf(bv, __shfl_xor_sync(0xffffffffu, bv, 2));
            if ((lane & 3) == 0) wval[row * 8 + nw] = bv;
        }
    __syncthreads();
    if (tid < MROWS) {
        float m = wval[tid * 8];
        #pragma unroll
        for (int w = 1; w < 8; ++w) m = fminf(m, wval[tid * 8 + w]);
        rmin[tid] = m;
    }
    __syncthreads();

    // pass 2: append candidates within MARGIN of the screened min
    #pragma unroll
    for (int mt = 0; mt < 4; ++mt)
        #pragma unroll
        for (int h = 0; h < 2; ++h) {
            const int row = mt * 16 + r0 + h * 8;
            const float thr = rmin[row] + MARGIN;
            #pragma unroll
            for (int nt = 0; nt < 4; ++nt) {
                const int col = nw * 32 + nt * 8 + c0;
                const float d0 = csq_s[col]     - 2.0f * acc[mt][nt][2*h];
                const float d1 = csq_s[col + 1] - 2.0f * acc[mt][nt][2*h+1];
                if (d0 <= thr) {
                    const int p = atomicAdd(&cnt[row], 1);
                    if (p < NCAND) cand[row * NCAND + p] = col;
                }
                if (d1 <= thr) {
                    const int p = atomicAdd(&cnt[row], 1);
                    if (p < NCAND) cand[row * NCAND + p] = col + 1;
                }
            }
        }
    __syncthreads();

    // rescore + gather, fused per warp: warp nw owns rows nw*8..nw*8+7.
    // Butterfly reduce leaves bit-identical sums in all lanes -> every lane
    // agrees on the winner; the warp gathers/writes the row immediately.
    const float4* cb4 = (const float4*)cb;
    float4* o4 = (float4*)out + (size_t)bid * MROWS * (H / 4);
    for (int rr = 0; rr < 8; ++rr) {
        const int row = nw * 8 + rr;
        const int n = cnt[row];
        int winner;
        if (n <= 1) {
            winner = (n == 1) ? cand[row * NCAND] : 0;
        } else {
            const bool full = (n > NCAND);   // overflow -> exact scan of all codes
            const int m = full ? CODES : n;
            float4 xr[8];
            const float4* xp = (const float4*)(src + (size_t)row * H);
            #pragma unroll
            for (int t = 0; t < 8; ++t) xr[t] = __ldg(xp + lane + 32 * t);
            float best = 3.4e38f; int bi = CODES;
            for (int j = 0; j < m; ++j) {
                const int c = full ? j : cand[row * NCAND + j];
                float p = 0.f;
                #pragma unroll
                for (int t = 0; t < 8; ++t) {
                    const float4 cv = __ldg(cb4 + (size_t)c * (H / 4) + lane + 32 * t);
                    p += xr[t].x * cv.x + xr[t].y * cv.y
                       + xr[t].z * cv.z + xr[t].w * cv.w;
                }
                #pragma unroll
                for (int o = 16; o; o >>= 1) p += __shfl_xor_sync(0xffffffffu, p, o);
                const float d = csq_s[c] - 2.0f * p;
                if (d < best || (d == best && c < bi)) { best = d; bi = c; }
            }
            winner = bi;
        }
        // warp-parallel gather: 8 independent LDG.128 + STG.128 per lane
        const float sc = (csq_s[winner] > 0.01f) ? 1.0f : 0.0f;   // ||c|| > 0.1
        const float4* cbr = cb4 + (size_t)winner * (H / 4);
        float4* orow = o4 + (size_t)row * (H / 4);
        float4 v[8];
        #pragma unroll
        for (int t = 0; t < 8; ++t) v[t] = __ldg(cbr + lane + 32 * t);
        #pragma unroll
        for (int t = 0; t < 8; ++t) {
            v[t].x *= sc; v[t].y *= sc; v[t].z *= sc; v[t].w *= sc;
            orow[lane + 32 * t] = v[t];
        }
    }
}

// ---------------------------------------------------------------- launch
extern "C" void kernel_launch(void* const* d_in, const int* in_sizes, int n_in,
                              void* d_out, int out_size) {
    const float* keys     = (const float*)d_in[0];
    const float* values   = (const float*)d_in[1];
    const float* codebook = (const float*)d_in[2];
    float* out = (float*)d_out;
    (void)in_sizes; (void)n_in; (void)out_size;

    cudaFuncSetAttribute(vq_kernel, cudaFuncAttributeMaxDynamicSharedMemorySize, SMEM_TOTAL);
    csq_kernel<<<CODES, 256>>>(codebook);
    bprep_kernel<<<CODES, 256>>>(codebook);
    vq_kernel<<<512, 256, SMEM_TOTAL>>>(keys, values, codebook, out);
}